// round 1
// baseline (speedup 1.0000x reference)
#include <cuda_runtime.h>
#include <math.h>

#define T_SEQ   4096
#define D_MODEL 1024
#define NH      16
#define DKH     64
#define E3      3072            // 3*D
#define ATT_SCALE 0.125f        // 1/sqrt(64)

// Scratch (device globals; no allocation allowed)
__device__ float g_qkv[T_SEQ * E3];     // [T, 3D]  48 MB
__device__ float g_ao [T_SEQ * D_MODEL];// [T, D]   16 MB

// ---------------------------------------------------------------------------
// C[M,N] = A[M,K] @ B[N,K]^T   (both row-major, K-contiguous)
// 128x128x16 tile, 256 threads, 8x8 per thread (split 4+4 to keep LDS.128
// conflict-free).
// ---------------------------------------------------------------------------
__global__ __launch_bounds__(256, 2)
void gemm_nt(const float* __restrict__ A, const float* __restrict__ B,
             float* __restrict__ C, int M, int N, int K)
{
    __shared__ float As[16][128];   // [k][m]
    __shared__ float Bs[16][128];   // [k][n]

    const int tid = threadIdx.x;
    const int tx  = tid & 15;       // 0..15
    const int ty  = tid >> 4;       // 0..15
    const int m0  = blockIdx.y * 128;
    const int n0  = blockIdx.x * 128;

    float acc[2][2][4][4];
    #pragma unroll
    for (int ri = 0; ri < 2; ri++)
        #pragma unroll
        for (int ci = 0; ci < 2; ci++)
            #pragma unroll
            for (int i = 0; i < 4; i++)
                #pragma unroll
                for (int j = 0; j < 4; j++)
                    acc[ri][ci][i][j] = 0.0f;

    for (int k0 = 0; k0 < K; k0 += 16) {
        // load 128x16 A-tile and B-tile (transposed into [k][m]/[k][n])
        #pragma unroll
        for (int t = 0; t < 2; t++) {
            int id  = tid + t * 256;       // 0..511
            int row = id >> 2;             // 0..127
            int c4  = id & 3;              // 0..3 (float4 within the 16-wide k)
            float4 va = *(const float4*)(A + (size_t)(m0 + row) * K + k0 + c4 * 4);
            As[c4 * 4 + 0][row] = va.x;
            As[c4 * 4 + 1][row] = va.y;
            As[c4 * 4 + 2][row] = va.z;
            As[c4 * 4 + 3][row] = va.w;
            float4 vb = *(const float4*)(B + (size_t)(n0 + row) * K + k0 + c4 * 4);
            Bs[c4 * 4 + 0][row] = vb.x;
            Bs[c4 * 4 + 1][row] = vb.y;
            Bs[c4 * 4 + 2][row] = vb.z;
            Bs[c4 * 4 + 3][row] = vb.w;
        }
        __syncthreads();

        #pragma unroll
        for (int k = 0; k < 16; k++) {
            float4 a0 = *(float4*)&As[k][ty * 4];
            float4 a1 = *(float4*)&As[k][64 + ty * 4];
            float4 b0 = *(float4*)&Bs[k][tx * 4];
            float4 b1 = *(float4*)&Bs[k][64 + tx * 4];
            float a[2][4] = {{a0.x, a0.y, a0.z, a0.w}, {a1.x, a1.y, a1.z, a1.w}};
            float b[2][4] = {{b0.x, b0.y, b0.z, b0.w}, {b1.x, b1.y, b1.z, b1.w}};
            #pragma unroll
            for (int ri = 0; ri < 2; ri++)
                #pragma unroll
                for (int i = 0; i < 4; i++)
                    #pragma unroll
                    for (int ci = 0; ci < 2; ci++)
                        #pragma unroll
                        for (int j = 0; j < 4; j++)
                            acc[ri][ci][i][j] += a[ri][i] * b[ci][j];
        }
        __syncthreads();
    }

    #pragma unroll
    for (int ri = 0; ri < 2; ri++)
        #pragma unroll
        for (int i = 0; i < 4; i++) {
            int row = m0 + ri * 64 + ty * 4 + i;
            #pragma unroll
            for (int ci = 0; ci < 2; ci++) {
                int col = n0 + ci * 64 + tx * 4;
                float4 out = make_float4(acc[ri][ci][i][0], acc[ri][ci][i][1],
                                         acc[ri][ci][i][2], acc[ri][ci][i][3]);
                *(float4*)(C + (size_t)row * N + col) = out;
            }
        }
}

// ---------------------------------------------------------------------------
// Flash attention (fp32), causal, with clamp(scores*scale, -10, 10) applied
// before masking (matches reference order). One CTA = (head, 64-query tile).
// Smem: Qst/Kst [dk][row] 64x64, Vs [s][dk] 64x64, Ps [64][68].
// ---------------------------------------------------------------------------
__global__ __launch_bounds__(256, 2)
void attn_kernel(const float* __restrict__ qkv, float* __restrict__ ao)
{
    extern __shared__ float sm[];
    float* Qst = sm;                 // 4096 floats [dk*64 + q]
    float* Kst = sm + 4096;          // 4096 floats [dk*64 + s]
    float* Vs  = sm + 8192;          // 4096 floats [s*64 + dk]
    float* Ps  = sm + 12288;         // 64*68 floats

    const int tid = threadIdx.x;
    const int tx  = tid & 15;
    const int ty  = tid >> 4;
    const int h   = blockIdx.y;
    const int qt  = (int)gridDim.x - 1 - (int)blockIdx.x;  // big tiles first
    const int q0  = qt * 64;

    const float* qbase = qkv + h * DKH;
    const float* kbase = qkv + D_MODEL + h * DKH;
    const float* vbase = qkv + 2 * D_MODEL + h * DKH;

    // load Q tile transposed: Qst[dk][r]
    #pragma unroll
    for (int t = 0; t < 4; t++) {
        int id  = tid + t * 256;       // 0..1023
        int row = id >> 4;             // 0..63
        int c4  = id & 15;             // 0..15
        float4 v = *(const float4*)(qbase + (size_t)(q0 + row) * E3 + c4 * 4);
        Qst[(c4 * 4 + 0) * 64 + row] = v.x;
        Qst[(c4 * 4 + 1) * 64 + row] = v.y;
        Qst[(c4 * 4 + 2) * 64 + row] = v.z;
        Qst[(c4 * 4 + 3) * 64 + row] = v.w;
    }

    float m[4], l[4], o[4][4];
    #pragma unroll
    for (int i = 0; i < 4; i++) {
        m[i] = -INFINITY;
        l[i] = 0.0f;
        #pragma unroll
        for (int j = 0; j < 4; j++) o[i][j] = 0.0f;
    }

    for (int jt = 0; jt <= qt; jt++) {
        const int kb = jt * 64;
        __syncthreads();   // prev iter done with Kst/Vs (and Q store visible)

        // load K (transposed) and V (natural) tiles
        #pragma unroll
        for (int t = 0; t < 4; t++) {
            int id  = tid + t * 256;
            int row = id >> 4;
            int c4  = id & 15;
            float4 kv = *(const float4*)(kbase + (size_t)(kb + row) * E3 + c4 * 4);
            Kst[(c4 * 4 + 0) * 64 + row] = kv.x;
            Kst[(c4 * 4 + 1) * 64 + row] = kv.y;
            Kst[(c4 * 4 + 2) * 64 + row] = kv.z;
            Kst[(c4 * 4 + 3) * 64 + row] = kv.w;
            float4 vv = *(const float4*)(vbase + (size_t)(kb + row) * E3 + c4 * 4);
            *(float4*)&Vs[row * 64 + c4 * 4] = vv;
        }
        __syncthreads();

        // S = Q @ K^T fragment (4x4)
        float s[4][4];
        #pragma unroll
        for (int i = 0; i < 4; i++)
            #pragma unroll
            for (int j = 0; j < 4; j++) s[i][j] = 0.0f;

        #pragma unroll 4
        for (int dk = 0; dk < 64; dk++) {
            float4 q4 = *(float4*)&Qst[dk * 64 + ty * 4];
            float4 k4 = *(float4*)&Kst[dk * 64 + tx * 4];
            float qa[4] = {q4.x, q4.y, q4.z, q4.w};
            float ka[4] = {k4.x, k4.y, k4.z, k4.w};
            #pragma unroll
            for (int i = 0; i < 4; i++)
                #pragma unroll
                for (int j = 0; j < 4; j++)
                    s[i][j] += qa[i] * ka[j];
        }

        // scale, clamp, causal mask (diagonal tile only)
        const bool diag = (jt == qt);
        #pragma unroll
        for (int i = 0; i < 4; i++)
            #pragma unroll
            for (int j = 0; j < 4; j++) {
                float v = fminf(fmaxf(s[i][j] * ATT_SCALE, -10.0f), 10.0f);
                if (diag && (tx * 4 + j > ty * 4 + i)) v = -1e30f;
                s[i][j] = v;
            }

        // online softmax update per row
        #pragma unroll
        for (int i = 0; i < 4; i++) {
            float rmax = fmaxf(fmaxf(s[i][0], s[i][1]), fmaxf(s[i][2], s[i][3]));
            #pragma unroll
            for (int off = 8; off >= 1; off >>= 1)
                rmax = fmaxf(rmax, __shfl_xor_sync(0xffffffffu, rmax, off));
            float mn = fmaxf(m[i], rmax);
            float alpha = expf(m[i] - mn);
            m[i] = mn;
            float rs = 0.0f;
            #pragma unroll
            for (int j = 0; j < 4; j++) {
                float p = expf(s[i][j] - mn);
                s[i][j] = p;
                rs += p;
            }
            #pragma unroll
            for (int off = 8; off >= 1; off >>= 1)
                rs += __shfl_xor_sync(0xffffffffu, rs, off);
            l[i] = alpha * l[i] + rs;
            #pragma unroll
            for (int j = 0; j < 4; j++) o[i][j] *= alpha;
            *(float4*)&Ps[(ty * 4 + i) * 68 + tx * 4] =
                make_float4(s[i][0], s[i][1], s[i][2], s[i][3]);
        }
        __syncthreads();

        // O += P @ V
        #pragma unroll 4
        for (int kk = 0; kk < 64; kk += 4) {
            float p[4][4];
            #pragma unroll
            for (int i = 0; i < 4; i++) {
                float4 p4 = *(float4*)&Ps[(ty * 4 + i) * 68 + kk];
                p[i][0] = p4.x; p[i][1] = p4.y; p[i][2] = p4.z; p[i][3] = p4.w;
            }
            #pragma unroll
            for (int u = 0; u < 4; u++) {
                float4 vv = *(float4*)&Vs[(kk + u) * 64 + tx * 4];
                float va[4] = {vv.x, vv.y, vv.z, vv.w};
                #pragma unroll
                for (int i = 0; i < 4; i++)
                    #pragma unroll
                    for (int j = 0; j < 4; j++)
                        o[i][j] += p[i][u] * va[j];
            }
        }
    }

    // normalize and write: ao[t, h*64 + dk]
    #pragma unroll
    for (int i = 0; i < 4; i++) {
        float inv = 1.0f / l[i];
        float4 out = make_float4(o[i][0] * inv, o[i][1] * inv,
                                 o[i][2] * inv, o[i][3] * inv);
        *(float4*)(ao + (size_t)(q0 + ty * 4 + i) * D_MODEL + h * DKH + tx * 4) = out;
    }
}

// ---------------------------------------------------------------------------
extern "C" void kernel_launch(void* const* d_in, const int* in_sizes, int n_in,
                              void* d_out, int out_size)
{
    const float* x    = (const float*)d_in[0];   // [1,4096,1024]
    const float* Wqkv = (const float*)d_in[1];   // [3072,1024]
    const float* Wout = (const float*)d_in[2];   // [1024,1024]
    float* out = (float*)d_out;                  // [1,4096,1024]

    float* qkvp = nullptr;
    float* aop  = nullptr;
    cudaGetSymbolAddress((void**)&qkvp, g_qkv);
    cudaGetSymbolAddress((void**)&aop,  g_ao);

    const int smem_attn = (4096 * 3 + 64 * 68) * (int)sizeof(float);  // 66560 B
    cudaFuncSetAttribute(attn_kernel,
                         cudaFuncAttributeMaxDynamicSharedMemorySize, smem_attn);

    // 1) QKV projection: [4096,3072] = x @ Wqkv^T
    dim3 g1(E3 / 128, T_SEQ / 128);
    gemm_nt<<<g1, 256>>>(x, Wqkv, qkvp, T_SEQ, E3, D_MODEL);

    // 2) causal flash attention
    dim3 g2(T_SEQ / 64, NH);
    attn_kernel<<<g2, 256, smem_attn>>>(qkvp, aop);

    // 3) output projection: [4096,1024] = ao @ Wout^T
    dim3 g3(D_MODEL / 128, T_SEQ / 128);
    gemm_nt<<<g3, 256>>>(aop, Wout, out, T_SEQ, D_MODEL, D_MODEL);
}

// round 11
// speedup vs baseline: 2.2913x; 2.2913x over previous
#include <cuda_runtime.h>
#include <cuda_bf16.h>
#include <cstdint>
#include <math.h>

#define T_SEQ   4096
#define D_MODEL 1024
#define NH      16
#define DKH     64
#define E3      3072
#define ATT_SCALE 0.125f

// Scratch (device globals; no allocation allowed)
__device__ float g_qkv[T_SEQ * E3];
__device__ float g_ao [T_SEQ * D_MODEL];

// ===========================================================================
// Warp-MMA helpers (m16n8k16 bf16, sm_80+ -> works on plain sm_103)
// ===========================================================================
__device__ __forceinline__ void mma_bf16(float* d, uint32_t a0, uint32_t a1,
                                         uint32_t a2, uint32_t a3,
                                         uint32_t b0, uint32_t b1)
{
    asm volatile(
        "mma.sync.aligned.m16n8k16.row.col.f32.bf16.bf16.f32 "
        "{%0,%1,%2,%3}, {%4,%5,%6,%7}, {%8,%9}, {%0,%1,%2,%3};"
        : "+f"(d[0]), "+f"(d[1]), "+f"(d[2]), "+f"(d[3])
        : "r"(a0), "r"(a1), "r"(a2), "r"(a3), "r"(b0), "r"(b1));
}

// pack (even, odd) floats -> bf16x2 (even in low half)
__device__ __forceinline__ uint32_t pack2(float e, float o) {
    __nv_bfloat162 t = __floats2bfloat162_rn(e, o);
    return *(uint32_t*)&t;
}

// split float4 -> hi bf16x2 pair + lo bf16x2 pair
__device__ __forceinline__ void split4(float4 v, uint32_t& h0, uint32_t& h1,
                                       uint32_t& l0, uint32_t& l1)
{
    __nv_bfloat162 H0 = __floats2bfloat162_rn(v.x, v.y);
    __nv_bfloat162 H1 = __floats2bfloat162_rn(v.z, v.w);
    __nv_bfloat162 L0 = __floats2bfloat162_rn(v.x - __bfloat162float(H0.x),
                                              v.y - __bfloat162float(H0.y));
    __nv_bfloat162 L1 = __floats2bfloat162_rn(v.z - __bfloat162float(H1.x),
                                              v.w - __bfloat162float(H1.y));
    h0 = *(uint32_t*)&H0; h1 = *(uint32_t*)&H1;
    l0 = *(uint32_t*)&L0; l1 = *(uint32_t*)&L1;
}

// ===========================================================================
// bf16x3 warp-MMA GEMM: C[M,N] = A[M,K] @ B[N,K]^T  (fp32 in/out)
// 128x128 CTA tile, 8 warps x (64x32), K chunks of 32, double-buffered smem.
// smem rows padded to 40 halves -> conflict-free fragment loads.
// ===========================================================================
#define GS 40                               // halves per smem row
#define GT_TEN 5120                         // 128*40 halves per tensor
#define GSM_TOTAL (8 * GT_TEN * 2)          // bytes: 81920

__global__ __launch_bounds__(256, 1)
void gemm_bf16x3(const float* __restrict__ A, const float* __restrict__ B,
                 float* __restrict__ C, int M, int N, int K)
{
    extern __shared__ char smraw[];
    __nv_bfloat16* sm = (__nv_bfloat16*)smraw;
    // tensor order per buffer: Ah, Al, Bh, Bl
    auto TEN = [&](int buf, int t) { return sm + (buf * 4 + t) * GT_TEN; };

    const int tid = threadIdx.x;
    const int wid = tid >> 5;
    const int lane = tid & 31;
    const int gid = lane >> 2;      // 0..7
    const int tg  = lane & 3;       // 0..3
    const int wm  = wid >> 2;       // 0..1
    const int wn  = wid & 3;        // 0..3
    const int m0  = blockIdx.y * 128;
    const int n0  = blockIdx.x * 128;

    float acc[4][4][4];
    #pragma unroll
    for (int mt = 0; mt < 4; mt++)
        #pragma unroll
        for (int nt = 0; nt < 4; nt++)
            #pragma unroll
            for (int c = 0; c < 4; c++) acc[mt][nt][c] = 0.0f;

    float4 ra[4], rb[4];
    auto g2r = [&](int k0) {
        #pragma unroll
        for (int i = 0; i < 4; i++) {
            int idx = tid + i * 256;
            int r = idx >> 3, c4 = idx & 7;
            ra[i] = *(const float4*)(A + (size_t)(m0 + r) * K + k0 + c4 * 4);
            rb[i] = *(const float4*)(B + (size_t)(n0 + r) * K + k0 + c4 * 4);
        }
    };
    auto r2s = [&](int buf) {
        #pragma unroll
        for (int i = 0; i < 4; i++) {
            int idx = tid + i * 256;
            int r = idx >> 3, c4 = idx & 7;
            uint32_t h0, h1, l0, l1;
            split4(ra[i], h0, h1, l0, l1);
            *(uint2*)(TEN(buf, 0) + r * GS + c4 * 4) = make_uint2(h0, h1);
            *(uint2*)(TEN(buf, 1) + r * GS + c4 * 4) = make_uint2(l0, l1);
            split4(rb[i], h0, h1, l0, l1);
            *(uint2*)(TEN(buf, 2) + r * GS + c4 * 4) = make_uint2(h0, h1);
            *(uint2*)(TEN(buf, 3) + r * GS + c4 * 4) = make_uint2(l0, l1);
        }
    };

    const int nch = K >> 5;
    g2r(0); r2s(0);
    __syncthreads();

    for (int c = 0; c < nch; c++) {
        if (c + 1 < nch) g2r((c + 1) << 5);
        const int b = c & 1;
        const __nv_bfloat16* Ah = TEN(b, 0);
        const __nv_bfloat16* Al = TEN(b, 1);
        const __nv_bfloat16* Bh = TEN(b, 2);
        const __nv_bfloat16* Bl = TEN(b, 3);

        #pragma unroll
        for (int h = 0; h < 2; h++) {
            const int kb = h * 16;
            uint32_t ah[4][4], al[4][4], bh[4][2], bl[4][2];
            #pragma unroll
            for (int mt = 0; mt < 4; mt++) {
                int row = wm * 64 + mt * 16 + gid;
                ah[mt][0] = *(const uint32_t*)(Ah + row * GS + kb + tg * 2);
                ah[mt][1] = *(const uint32_t*)(Ah + (row + 8) * GS + kb + tg * 2);
                ah[mt][2] = *(const uint32_t*)(Ah + row * GS + kb + 8 + tg * 2);
                ah[mt][3] = *(const uint32_t*)(Ah + (row + 8) * GS + kb + 8 + tg * 2);
                al[mt][0] = *(const uint32_t*)(Al + row * GS + kb + tg * 2);
                al[mt][1] = *(const uint32_t*)(Al + (row + 8) * GS + kb + tg * 2);
                al[mt][2] = *(const uint32_t*)(Al + row * GS + kb + 8 + tg * 2);
                al[mt][3] = *(const uint32_t*)(Al + (row + 8) * GS + kb + 8 + tg * 2);
            }
            #pragma unroll
            for (int nt = 0; nt < 4; nt++) {
                int col = wn * 32 + nt * 8 + gid;
                bh[nt][0] = *(const uint32_t*)(Bh + col * GS + kb + tg * 2);
                bh[nt][1] = *(const uint32_t*)(Bh + col * GS + kb + 8 + tg * 2);
                bl[nt][0] = *(const uint32_t*)(Bl + col * GS + kb + tg * 2);
                bl[nt][1] = *(const uint32_t*)(Bl + col * GS + kb + 8 + tg * 2);
            }
            #pragma unroll
            for (int mt = 0; mt < 4; mt++)
                #pragma unroll
                for (int nt = 0; nt < 4; nt++) {
                    mma_bf16(acc[mt][nt], ah[mt][0], ah[mt][1], ah[mt][2], ah[mt][3],
                             bh[nt][0], bh[nt][1]);
                    mma_bf16(acc[mt][nt], ah[mt][0], ah[mt][1], ah[mt][2], ah[mt][3],
                             bl[nt][0], bl[nt][1]);
                    mma_bf16(acc[mt][nt], al[mt][0], al[mt][1], al[mt][2], al[mt][3],
                             bh[nt][0], bh[nt][1]);
                }
        }
        __syncthreads();
        if (c + 1 < nch) {
            r2s(b ^ 1);
            __syncthreads();
        }
    }

    #pragma unroll
    for (int mt = 0; mt < 4; mt++) {
        int r0 = m0 + wm * 64 + mt * 16 + gid;
        #pragma unroll
        for (int nt = 0; nt < 4; nt++) {
            int col = n0 + wn * 32 + nt * 8 + tg * 2;
            *(float2*)(C + (size_t)r0 * N + col) =
                make_float2(acc[mt][nt][0], acc[mt][nt][1]);
            *(float2*)(C + (size_t)(r0 + 8) * N + col) =
                make_float2(acc[mt][nt][2], acc[mt][nt][3]);
        }
    }
}

// ===========================================================================
// bf16x3 warp-MMA flash attention, causal, clamp before mask.
// CTA = (head, 128-query tile), 8 warps x 16 query rows, 64-key tiles.
// S fragments stay in registers through softmax; reused as P A-fragments.
// ===========================================================================
#define QS 72                         // halves per smem row (64 + 8 pad)
// smem offsets in halves:
#define AQH 0
#define AQL 9216
#define AKH 18432
#define AKL 23040
#define AVH 27648
#define AVL 32256
#define ASM_TOTAL (36864 * 2)         // 73728 bytes

__global__ __launch_bounds__(256, 1)
void attn_mma(const float* __restrict__ qkv, float* __restrict__ ao)
{
    extern __shared__ char smraw[];
    __nv_bfloat16* sm = (__nv_bfloat16*)smraw;

    const int tid = threadIdx.x;
    const int wid = tid >> 5;
    const int lane = tid & 31;
    const int gid = lane >> 2;
    const int tg  = lane & 3;
    const int h   = blockIdx.y;
    const int qt  = 31 - (int)blockIdx.x;   // big tiles first
    const int q0  = qt * 128;

    const float* qbase = qkv + h * DKH;
    const float* kbase = qkv + D_MODEL + h * DKH;
    const float* vbase = qkv + 2 * D_MODEL + h * DKH;

    // ---- load Q tile (128 x 64) as hi/lo bf16 ----
    #pragma unroll
    for (int i = 0; i < 8; i++) {
        int idx = tid + i * 256;
        int r = idx >> 4, c4 = idx & 15;
        float4 v = *(const float4*)(qbase + (size_t)(q0 + r) * E3 + c4 * 4);
        uint32_t h0, h1, l0, l1;
        split4(v, h0, h1, l0, l1);
        *(uint2*)(sm + AQH + r * QS + c4 * 4) = make_uint2(h0, h1);
        *(uint2*)(sm + AQL + r * QS + c4 * 4) = make_uint2(l0, l1);
    }
    __syncthreads();

    float o[8][4];
    #pragma unroll
    for (int nt = 0; nt < 8; nt++)
        #pragma unroll
        for (int c = 0; c < 4; c++) o[nt][c] = 0.0f;
    float mrow[2] = {-INFINITY, -INFINITY};
    float lrow[2] = {0.0f, 0.0f};

    const int r0 = q0 + wid * 16 + gid;   // this thread's two query rows
    const int r1 = r0 + 8;
    const int nk = 2 * (qt + 1);

    for (int it = 0; it < nk; it++) {
        const int kb = it * 64;
        if (it) __syncthreads();          // smem reuse barrier

        // ---- load K (natural) and V (transposed) as hi/lo bf16 ----
        #pragma unroll
        for (int i = 0; i < 4; i++) {
            int idx = tid + i * 256;
            int rr = idx >> 4, c4 = idx & 15;
            float4 kv = *(const float4*)(kbase + (size_t)(kb + rr) * E3 + c4 * 4);
            uint32_t h0, h1, l0, l1;
            split4(kv, h0, h1, l0, l1);
            *(uint2*)(sm + AKH + rr * QS + c4 * 4) = make_uint2(h0, h1);
            *(uint2*)(sm + AKL + rr * QS + c4 * 4) = make_uint2(l0, l1);

            float4 vv = *(const float4*)(vbase + (size_t)(kb + rr) * E3 + c4 * 4);
            float va[4] = {vv.x, vv.y, vv.z, vv.w};
            #pragma unroll
            for (int e = 0; e < 4; e++) {
                int dk = c4 * 4 + e;
                __nv_bfloat16 hb = __float2bfloat16_rn(va[e]);
                __nv_bfloat16 lb = __float2bfloat16_rn(va[e] - __bfloat162float(hb));
                sm[AVH + dk * QS + rr] = hb;
                sm[AVL + dk * QS + rr] = lb;
            }
        }
        __syncthreads();

        // ---- S = Q @ K^T (bf16x3) ----
        float s[8][4];
        #pragma unroll
        for (int nt = 0; nt < 8; nt++)
            #pragma unroll
            for (int c = 0; c < 4; c++) s[nt][c] = 0.0f;

        #pragma unroll
        for (int kc = 0; kc < 4; kc++) {
            const int kb16 = kc * 16;
            const int row = wid * 16 + gid;
            uint32_t qh0 = *(const uint32_t*)(sm + AQH + row * QS + kb16 + tg * 2);
            uint32_t qh1 = *(const uint32_t*)(sm + AQH + (row + 8) * QS + kb16 + tg * 2);
            uint32_t qh2 = *(const uint32_t*)(sm + AQH + row * QS + kb16 + 8 + tg * 2);
            uint32_t qh3 = *(const uint32_t*)(sm + AQH + (row + 8) * QS + kb16 + 8 + tg * 2);
            uint32_t ql0 = *(const uint32_t*)(sm + AQL + row * QS + kb16 + tg * 2);
            uint32_t ql1 = *(const uint32_t*)(sm + AQL + (row + 8) * QS + kb16 + tg * 2);
            uint32_t ql2 = *(const uint32_t*)(sm + AQL + row * QS + kb16 + 8 + tg * 2);
            uint32_t ql3 = *(const uint32_t*)(sm + AQL + (row + 8) * QS + kb16 + 8 + tg * 2);
            #pragma unroll
            for (int nt = 0; nt < 8; nt++) {
                int col = nt * 8 + gid;
                uint32_t kh0 = *(const uint32_t*)(sm + AKH + col * QS + kb16 + tg * 2);
                uint32_t kh1 = *(const uint32_t*)(sm + AKH + col * QS + kb16 + 8 + tg * 2);
                uint32_t kl0 = *(const uint32_t*)(sm + AKL + col * QS + kb16 + tg * 2);
                uint32_t kl1 = *(const uint32_t*)(sm + AKL + col * QS + kb16 + 8 + tg * 2);
                mma_bf16(s[nt], qh0, qh1, qh2, qh3, kh0, kh1);
                mma_bf16(s[nt], qh0, qh1, qh2, qh3, kl0, kl1);
                mma_bf16(s[nt], ql0, ql1, ql2, ql3, kh0, kh1);
            }
        }

        // ---- scale, clamp, causal mask ----
        #pragma unroll
        for (int nt = 0; nt < 8; nt++)
            #pragma unroll
            for (int c = 0; c < 4; c++) {
                int col = kb + nt * 8 + tg * 2 + (c & 1);
                int row = (c < 2) ? r0 : r1;
                float v = fminf(fmaxf(s[nt][c] * ATT_SCALE, -10.0f), 10.0f);
                if (col > row) v = -1e30f;
                s[nt][c] = v;
            }

        // ---- online softmax (per row-half; group-of-4 shfl reduce) ----
        float alpha[2];
        #pragma unroll
        for (int hf = 0; hf < 2; hf++) {
            float rmax = -INFINITY;
            #pragma unroll
            for (int nt = 0; nt < 8; nt++) {
                rmax = fmaxf(rmax, s[nt][hf * 2]);
                rmax = fmaxf(rmax, s[nt][hf * 2 + 1]);
            }
            rmax = fmaxf(rmax, __shfl_xor_sync(0xffffffffu, rmax, 1));
            rmax = fmaxf(rmax, __shfl_xor_sync(0xffffffffu, rmax, 2));
            float mn = fmaxf(mrow[hf], rmax);
            alpha[hf] = expf(mrow[hf] - mn);
            mrow[hf] = mn;
            float rs = 0.0f;
            #pragma unroll
            for (int nt = 0; nt < 8; nt++) {
                float p0 = expf(s[nt][hf * 2]     - mn);
                float p1 = expf(s[nt][hf * 2 + 1] - mn);
                s[nt][hf * 2]     = p0;
                s[nt][hf * 2 + 1] = p1;
                rs += p0 + p1;
            }
            rs += __shfl_xor_sync(0xffffffffu, rs, 1);
            rs += __shfl_xor_sync(0xffffffffu, rs, 2);
            lrow[hf] = alpha[hf] * lrow[hf] + rs;
            #pragma unroll
            for (int nt = 0; nt < 8; nt++) {
                o[nt][hf * 2]     *= alpha[hf];
                o[nt][hf * 2 + 1] *= alpha[hf];
            }
        }

        // ---- O += P @ V (bf16x3); P packed from S fragments in registers ----
        #pragma unroll
        for (int kc = 0; kc < 4; kc++) {
            const int n0t = 2 * kc, n1t = 2 * kc + 1;
            // hi/lo A fragments of P
            float p00 = s[n0t][0], p01 = s[n0t][1], p02 = s[n0t][2], p03 = s[n0t][3];
            float p10 = s[n1t][0], p11 = s[n1t][1], p12 = s[n1t][2], p13 = s[n1t][3];
            __nv_bfloat162 H;
            uint32_t pah[4], pal[4];
            H = __floats2bfloat162_rn(p00, p01); pah[0] = *(uint32_t*)&H;
            pal[0] = pack2(p00 - __bfloat162float(H.x), p01 - __bfloat162float(H.y));
            H = __floats2bfloat162_rn(p02, p03); pah[1] = *(uint32_t*)&H;
            pal[1] = pack2(p02 - __bfloat162float(H.x), p03 - __bfloat162float(H.y));
            H = __floats2bfloat162_rn(p10, p11); pah[2] = *(uint32_t*)&H;
            pal[2] = pack2(p10 - __bfloat162float(H.x), p11 - __bfloat162float(H.y));
            H = __floats2bfloat162_rn(p12, p13); pah[3] = *(uint32_t*)&H;
            pal[3] = pack2(p12 - __bfloat162float(H.x), p13 - __bfloat162float(H.y));

            const int kb16 = kc * 16;
            #pragma unroll
            for (int nt = 0; nt < 8; nt++) {
                int dk = nt * 8 + gid;
                uint32_t vh0 = *(const uint32_t*)(sm + AVH + dk * QS + kb16 + tg * 2);
                uint32_t vh1 = *(const uint32_t*)(sm + AVH + dk * QS + kb16 + 8 + tg * 2);
                uint32_t vl0 = *(const uint32_t*)(sm + AVL + dk * QS + kb16 + tg * 2);
                uint32_t vl1 = *(const uint32_t*)(sm + AVL + dk * QS + kb16 + 8 + tg * 2);
                mma_bf16(o[nt], pah[0], pah[1], pah[2], pah[3], vh0, vh1);
                mma_bf16(o[nt], pah[0], pah[1], pah[2], pah[3], vl0, vl1);
                mma_bf16(o[nt], pal[0], pal[1], pal[2], pal[3], vh0, vh1);
            }
        }
    }

    // ---- normalize and write out ----
    float inv0 = 1.0f / lrow[0];
    float inv1 = 1.0f / lrow[1];
    #pragma unroll
    for (int nt = 0; nt < 8; nt++) {
        int col = h * DKH + nt * 8 + tg * 2;
        *(float2*)(ao + (size_t)r0 * D_MODEL + col) =
            make_float2(o[nt][0] * inv0, o[nt][1] * inv0);
        *(float2*)(ao + (size_t)r1 * D_MODEL + col) =
            make_float2(o[nt][2] * inv1, o[nt][3] * inv1);
    }
}

// ===========================================================================
extern "C" void kernel_launch(void* const* d_in, const int* in_sizes, int n_in,
                              void* d_out, int out_size)
{
    const float* x    = (const float*)d_in[0];
    const float* Wqkv = (const float*)d_in[1];
    const float* Wout = (const float*)d_in[2];
    float* out = (float*)d_out;

    float* qkvp = nullptr;
    float* aop  = nullptr;
    cudaGetSymbolAddress((void**)&qkvp, g_qkv);
    cudaGetSymbolAddress((void**)&aop,  g_ao);

    cudaFuncSetAttribute(gemm_bf16x3,
                         cudaFuncAttributeMaxDynamicSharedMemorySize, GSM_TOTAL);
    cudaFuncSetAttribute(attn_mma,
                         cudaFuncAttributeMaxDynamicSharedMemorySize, ASM_TOTAL);

    // 1) QKV projection: [4096,3072] = x @ Wqkv^T
    dim3 g1(E3 / 128, T_SEQ / 128);
    gemm_bf16x3<<<g1, 256, GSM_TOTAL>>>(x, Wqkv, qkvp, T_SEQ, E3, D_MODEL);

    // 2) causal flash attention (warp-MMA bf16x3)
    dim3 g2(T_SEQ / 128, NH);
    attn_mma<<<g2, 256, ASM_TOTAL>>>(qkvp, aop);

    // 3) output projection: [4096,1024] = ao @ Wout^T
    dim3 g3(D_MODEL / 128, T_SEQ / 128);
    gemm_bf16x3<<<g3, 256, GSM_TOTAL>>>(aop, Wout, out, T_SEQ, D_MODEL, D_MODEL);
}